// round 16
// baseline (speedup 1.0000x reference)
#include <cuda_runtime.h>
#include <cuda_fp16.h>
#include <stdint.h>

#define BATCH 16
#define CIN   128
#define HH    128
#define WW    128
#define OCH   256
#define HW    (HH*WW)
#define KTOT  1152.0f
#define BADCNT 576.0f

// ---------------- scratch (no allocations allowed) ----------------
__device__ float g_pm  [BATCH*HW];
__device__ float g_bad [BATCH*HW];
__device__ float g_csum[BATCH*HW];
__device__ float g_ccnt[BATCH*HW];
__device__ float g_csum4[BATCH*4*HW];   // per-cg partials from xprep
__device__ float g_ccnt4[BATCH*4*HW];
// B fragments (single fp16 chain), packed for LDS.128 (2 n-tiles per load):
// [ tap*4+cg ][ ntp16 ][ kt2 ][ lane32 ][ jj2 ][ r2 ]  (u32); block = 4096 words = 16KB
#define WF_WORDS (36*4096)
__device__ uint32_t g_wf[WF_WORDS];
// Pre-transposed fp16 input: [b][cg][rp 130][wc 132][ch 32], 16B-chunk swizzled.
__device__ __align__(128) uint16_t g_xt[(size_t)BATCH*4*130*4224];

__device__ __forceinline__ bool nan_bits(float v) {
    return (__float_as_uint(v) & 0x7fffffffu) > 0x7f800000u;
}
__device__ __forceinline__ uint32_t smem_u32(const void* p) {
    return (uint32_t)__cvta_generic_to_shared(p);
}
__device__ __forceinline__ void cp16(uint32_t dst, const void* src) {
    asm volatile("cp.async.cg.shared.global [%0], [%1], 16;" :: "r"(dst), "l"(src));
}
__device__ __forceinline__ void mma16816(float* c, const uint32_t* a, uint32_t b0, uint32_t b1) {
    asm volatile(
        "mma.sync.aligned.m16n8k16.row.col.f32.f16.f16.f32 "
        "{%0,%1,%2,%3}, {%4,%5,%6,%7}, {%8,%9}, {%0,%1,%2,%3};"
        : "+f"(c[0]), "+f"(c[1]), "+f"(c[2]), "+f"(c[3])
        : "r"(a[0]), "r"(a[1]), "r"(a[2]), "r"(a[3]), "r"(b0), "r"(b1));
}

// ---------------- stats1b: reduce 4 cg partials -> per-pixel ----------------
__global__ void stats1b_kernel() {
    int idx = blockIdx.x * blockDim.x + threadIdx.x;
    if (idx >= BATCH * HW) return;
    int b  = idx / HW;
    int hw = idx - b * HW;
    float s = 0.f, cnt = 0.f;
    #pragma unroll
    for (int cg = 0; cg < 4; cg++) {
        s   += g_csum4[(b * 4 + cg) * HW + hw];
        cnt += g_ccnt4[(b * 4 + cg) * HW + hw];
    }
    g_csum[idx] = s;
    g_ccnt[idx] = cnt;
}

__global__ void stats2_kernel() {
    int idx = blockIdx.x * blockDim.x + threadIdx.x;
    if (idx >= BATCH * HW) return;
    int b  = idx / HW;
    int hw = idx - b * HW;
    int oh = hw / WW;
    int ow = hw - oh * WW;
    float vs = 0.f, cnt = 0.f;
    #pragma unroll
    for (int kh = -1; kh <= 1; kh++) {
        int ih = oh + kh;
        if (ih < 0 || ih >= HH) continue;
        #pragma unroll
        for (int kw = -1; kw <= 1; kw++) {
            int iw = ow + kw;
            if (iw < 0 || iw >= WW) continue;
            int g = b * HW + ih * WW + iw;
            vs  += g_csum[g];
            cnt += g_ccnt[g];
        }
    }
    float valid = KTOT - cnt;
    g_pm[idx]  = vs / fmaxf(valid, 1.f);
    g_bad[idx] = (cnt >= BADCNT) ? 1.f : 0.f;
}

// ---------------- weight prep: fp16 round into packed B-fragment layout ----------------
__global__ void wprep_kernel(const float* __restrict__ w) {
    int idx = blockIdx.x * blockDim.x + threadIdx.x;
    if (idx >= WF_WORDS) return;
    int r    = idx & 1;
    int jj   = (idx >> 1) & 1;
    int lane = (idx >> 2) & 31;
    int kt   = (idx >> 7) & 1;
    int ntp  = (idx >> 8) & 15;
    int tcg  = idx >> 12;              // tap*4+cg
    int cg   = tcg & 3;
    int tap  = tcg >> 2;

    int nt = ntp * 2 + jj;
    int oc = nt * 8 + (lane >> 2);
    int c0 = cg * 32 + kt * 16 + (lane & 3) * 2 + r * 8;

    uint32_t pack = 0;
    #pragma unroll
    for (int e = 0; e < 2; e++) {
        float wv = w[((size_t)oc * CIN + (c0 + e)) * 9 + tap];
        pack |= (uint32_t)__half_as_ushort(__float2half_rn(wv)) << (e * 16);
    }
    g_wf[idx] = pack;
}

// ---------------- x prep: fp16 transpose + swizzle + fused channel stats ----------------
__global__ void xprep_kernel(const float* __restrict__ x) {
    __shared__ float tile[32 * 133];
    const int rp = blockIdx.x;   // 0..129
    const int cg = blockIdx.y;
    const int b  = blockIdx.z;
    const int t  = threadIdx.x;
    uint32_t* dst = (uint32_t*)(g_xt + (((size_t)(b * 4 + cg) * 130 + rp) * 4224));

    if (rp == 0 || rp == 129) {
        for (int i = t; i < 2112; i += 256) dst[i] = 0;
        return;
    }
    const int row = rp - 1;
    const float* src = x + ((size_t)(b * CIN + cg * 32) * HH + row) * WW;
    for (int i = t; i < 4096; i += 256) {
        int c = i >> 7, col = i & 127;
        tile[c * 133 + col + 1] = src[(size_t)c * HW + col];
    }
    if (t < 128) {
        int c = t & 31, which = t >> 5;
        int wc = (which == 0) ? 0 : (128 + which);
        tile[c * 133 + wc] = 0.f;
    }
    __syncthreads();
    for (int i = t; i < 2112; i += 256) {
        int wc = i >> 4, cp = i & 15;
        float f0 = tile[(2 * cp) * 133 + wc];
        float f1 = tile[(2 * cp + 1) * 133 + wc];
        uint32_t h0 = __half_as_ushort(__float2half_rn(f0));
        uint32_t h1 = __half_as_ushort(__float2half_rn(f1));
        int chunk  = cp >> 2;
        int chunks = (chunk ^ (wc & 3) ^ ((wc >> 2) & 3)) & 3;
        dst[wc * 16 + chunks * 4 + (cp & 3)] = (h1 << 16) | h0;
    }
    if (t < 128) {
        float s = 0.f, cnt = 0.f;
        #pragma unroll 8
        for (int c = 0; c < 32; c++) {
            float v = tile[c * 133 + t + 1];
            bool n = nan_bits(v);
            cnt += n ? 1.f : 0.f;
            s   += n ? 0.f : v;
        }
        int o = (b * 4 + cg) * HW + row * WW + t;
        g_csum4[o] = s;
        g_ccnt4[o] = cnt;
    }
}

// ---------------- main conv: cadence-3 pipelined fp16 mma.sync ----------------
// CTA: 512 thr, 16 warps (2m x 8n). M=128 x N=256. K=1152 = 36 taps.
// 6-deep af/bf, 4-deep raw; lead 3; barrier every 3 phases.
#define THREADS 512
#define RAWBYTES 8448

#define OFF_BF   0u               // 6 x 16384 = 98304
#define OFF_AF   98304u           // 6 x 8192  = 49152
#define OFF_RAW  147456u          // 4 x 8448  = 33792
#define OFF_PMH  181248u          // 256
#define OFF_BAD  181504u          // 512
#define OFF_BIAS 182016u          // 1024
#define SMEMSZ   183040u

__device__ __forceinline__ void issue_stage_nc(uint32_t raw_addr, int b, int oh, int R, int tid) {
    int cg = R / 3, kh = R - cg * 3;
    const char* src = (const char*)(g_xt + (((size_t)(b * 4 + cg) * 130 + (oh + kh)) * 4224));
    cp16(raw_addr + (uint32_t)tid * 16u, src + tid * 16);
    if (tid < 16) cp16(raw_addr + (uint32_t)(512 + tid) * 16u, src + (512 + tid) * 16);
}

__device__ __forceinline__ void issue_bf_nc(uint32_t bf_addr, int tap, int tid) {
    int R = tap / 3, kw = tap - R * 3;
    int cg = R / 3, kh = R - cg * 3;
    int tcg = (kh * 3 + kw) * 4 + cg;
    const char* src = (const char*)g_wf + (size_t)tcg * 16384;
    uint32_t d = bf_addr + (uint32_t)tid * 16u;
    cp16(d,        src + tid * 16);
    cp16(d + 8192, src + 8192 + tid * 16);
}

__device__ __forceinline__ void build_af(uint32_t* af, const char* raw,
                                         const uint16_t* pmh, int kw, int tid) {
    // a0:{m,k} a1:{m+8,k} a2:{m,k+8} a3:{m+8,k+8}
    #pragma unroll
    for (int it = 0; it < 4; it++) {
        int w    = tid + it * THREADS;
        int reg  = w & 3;
        int ln   = (w >> 2) & 31;
        int tile = w >> 7;
        int kt   = tile & 1;
        int mt   = tile >> 1;
        int m    = mt * 16 + ((reg & 1) << 3) + (ln >> 2);
        int k    = kt * 16 + ((reg >> 1) << 3) + (ln & 3) * 2;
        int wc   = m + kw;
        int chunks = ((k >> 3) ^ (wc & 3) ^ ((wc >> 2) & 3)) & 3;
        uint32_t off = (uint32_t)(wc * 64 + chunks * 16 + (k & 7) * 2);
        uint32_t pair = *(const uint32_t*)(raw + off);
        uint32_t pmv  = (uint32_t)pmh[m];
        uint32_t lo = pair & 0xffffu, hi = pair >> 16;
        if ((lo & 0x7fffu) > 0x7c00u) lo = pmv;
        if ((hi & 0x7fffu) > 0x7c00u) hi = pmv;
        af[w] = (hi << 16) | lo;
    }
}

__device__ __forceinline__ void mma_tap(float acc[4][4][4], const uint32_t* af,
                                        const uint32_t* bf, int mt0, int ntp0, int lane) {
    #pragma unroll
    for (int kt = 0; kt < 2; kt++) {
        uint32_t a[4][4];
        #pragma unroll
        for (int i = 0; i < 4; i++) {
            uint4 av = *(const uint4*)&af[(((mt0 + i) * 2 + kt) * 32 + lane) * 4];
            a[i][0] = av.x; a[i][1] = av.y; a[i][2] = av.z; a[i][3] = av.w;
        }
        #pragma unroll
        for (int jp = 0; jp < 2; jp++) {
            uint4 bv = *(const uint4*)&bf[(((ntp0 + jp) * 2 + kt) * 32 + lane) * 4];
            #pragma unroll
            for (int i = 0; i < 4; i++) {
                mma16816(acc[i][jp * 2],     a[i], bv.x, bv.y);
                mma16816(acc[i][jp * 2 + 1], a[i], bv.z, bv.w);
            }
        }
    }
}

// One pipeline phase; PH in [0,12) compile-time. t0 % 12 == 0 so all slot
// indices ((PH+3)%6, ((PH+3)/3)%4, (PH/3+3)%4, kw=PH%3) constant-fold.
template<int PH>
__device__ __forceinline__ void phase(float acc[4][4][4], char* sm, uint32_t smb,
                                      int t0, int b, int oh, int mt0, int ntp0,
                                      int lane, int tid, const uint16_t* pmh) {
    const int t = t0 + PH;
    if (t + 3 < 36)
        issue_bf_nc(smb + OFF_BF + (uint32_t)(((PH + 3) % 6) * 16384), t + 3, tid);
    if ((PH % 3) == 0) {
        int R = t / 3;
        if (R + 3 <= 11)
            issue_stage_nc(smb + OFF_RAW + (uint32_t)((((PH / 3) + 3) % 4) * RAWBYTES),
                           b, oh, R + 3, tid);
    }
    asm volatile("cp.async.commit_group;");
    if (t + 3 < 36)
        build_af((uint32_t*)(sm + OFF_AF + ((PH + 3) % 6) * 8192),
                 sm + OFF_RAW + (((PH + 3) / 3) % 4) * RAWBYTES,
                 pmh, PH % 3, tid);
    mma_tap(acc, (const uint32_t*)(sm + OFF_AF + (PH % 6) * 8192),
            (const uint32_t*)(sm + OFF_BF + (PH % 6) * 16384),
            mt0, ntp0, lane);
    if ((PH % 3) == 2) {
        asm volatile("cp.async.wait_group 0;");
        __syncthreads();
    }
}

__global__ __launch_bounds__(THREADS, 1)
void conv_mma_kernel(const float* __restrict__ x,
                     const float* __restrict__ bias,
                     float* __restrict__ out)
{
    extern __shared__ char sm[];
    uint16_t* s_pmh  = (uint16_t*)(sm + OFF_PMH);
    float*    s_bad  = (float*)(sm + OFF_BAD);
    float*    s_bias = (float*)(sm + OFF_BIAS);
    const uint32_t smb = smem_u32(sm);

    const int tid  = threadIdx.x;
    const int lane = tid & 31;
    const int wid  = tid >> 5;
    const int oh   = blockIdx.x;
    const int b    = blockIdx.y;
    const int mt0  = (wid >> 3) * 4;
    const int ntp0 = (wid & 7) * 2;

    if (tid < 128) {
        int g = b * HW + oh * WW + tid;
        s_pmh[tid] = __half_as_ushort(__float2half_rn(g_pm[g]));
        s_bad[tid] = g_bad[g];
    }
    if (tid < 256) s_bias[tid] = bias[tid];

    float acc[4][4][4];
    #pragma unroll
    for (int i = 0; i < 4; i++)
        #pragma unroll
        for (int j = 0; j < 4; j++)
            #pragma unroll
            for (int r = 0; r < 4; r++) acc[i][j][r] = 0.f;

    // ---- prologue: stage rows 0..2; bf taps 0..2; build taps 0..2 (all read row 0) ----
    issue_stage_nc(smb + OFF_RAW,                b, oh, 0, tid);
    issue_stage_nc(smb + OFF_RAW + RAWBYTES,     b, oh, 1, tid);
    issue_stage_nc(smb + OFF_RAW + 2 * RAWBYTES, b, oh, 2, tid);
    asm volatile("cp.async.commit_group;");
    asm volatile("cp.async.wait_group 0;");
    __syncthreads();
    issue_bf_nc(smb + OFF_BF,          0, tid);
    issue_bf_nc(smb + OFF_BF + 16384u, 1, tid);
    issue_bf_nc(smb + OFF_BF + 32768u, 2, tid);
    asm volatile("cp.async.commit_group;");
    build_af((uint32_t*)(sm + OFF_AF),         sm + OFF_RAW, s_pmh, 0, tid);
    build_af((uint32_t*)(sm + OFF_AF + 8192),  sm + OFF_RAW, s_pmh, 1, tid);
    build_af((uint32_t*)(sm + OFF_AF + 16384), sm + OFF_RAW, s_pmh, 2, tid);
    asm volatile("cp.async.wait_group 0;");
    __syncthreads();

    // ---- main loop: 3 x 12 phases, barrier every 3 phases ----
    for (int it3 = 0; it3 < 3; it3++) {
        int t0 = it3 * 12;
        phase<0>(acc, sm, smb, t0, b, oh, mt0, ntp0, lane, tid, s_pmh);
        phase<1>(acc, sm, smb, t0, b, oh, mt0, ntp0, lane, tid, s_pmh);
        phase<2>(acc, sm, smb, t0, b, oh, mt0, ntp0, lane, tid, s_pmh);
        phase<3>(acc, sm, smb, t0, b, oh, mt0, ntp0, lane, tid, s_pmh);
        phase<4>(acc, sm, smb, t0, b, oh, mt0, ntp0, lane, tid, s_pmh);
        phase<5>(acc, sm, smb, t0, b, oh, mt0, ntp0, lane, tid, s_pmh);
        phase<6>(acc, sm, smb, t0, b, oh, mt0, ntp0, lane, tid, s_pmh);
        phase<7>(acc, sm, smb, t0, b, oh, mt0, ntp0, lane, tid, s_pmh);
        phase<8>(acc, sm, smb, t0, b, oh, mt0, ntp0, lane, tid, s_pmh);
        phase<9>(acc, sm, smb, t0, b, oh, mt0, ntp0, lane, tid, s_pmh);
        phase<10>(acc, sm, smb, t0, b, oh, mt0, ntp0, lane, tid, s_pmh);
        phase<11>(acc, sm, smb, t0, b, oh, mt0, ntp0, lane, tid, s_pmh);
    }

    // ---- epilogue: bias + bad->NaN, direct stores ----
    const float NANF = __uint_as_float(0x7fc00000u);
    #pragma unroll
    for (int i = 0; i < 4; i++) {
        #pragma unroll
        for (int r = 0; r < 4; r++) {
            int m = (mt0 + i) * 16 + ((r >> 1) << 3) + (lane >> 2);
            bool isbad = s_bad[m] != 0.f;
            #pragma unroll
            for (int j = 0; j < 4; j++) {
                int n = ((wid & 7) * 4 + j) * 8 + (lane & 3) * 2 + (r & 1);
                float v = acc[i][j][r] + s_bias[n];
                out[(((size_t)b * OCH + n) * HH + oh) * WW + m] = isbad ? NANF : v;
            }
        }
    }
}

// ---------------------------------------------------------------------------
extern "C" void kernel_launch(void* const* d_in, const int* in_sizes, int n_in,
                              void* d_out, int out_size) {
    const float* x    = (const float*)d_in[0];
    const float* wk   = (const float*)d_in[1];
    const float* bias = (const float*)d_in[2];
    float* out        = (float*)d_out;

    int npix = BATCH * HW;
    {
        dim3 g(130, 4, BATCH);
        xprep_kernel<<<g, 256>>>(x);
    }
    stats1b_kernel<<<(npix + 255) / 256, 256>>>();
    stats2_kernel<<<(npix + 255) / 256, 256>>>();
    wprep_kernel<<<(WF_WORDS + 255) / 256, 256>>>(wk);

    cudaFuncSetAttribute(conv_mma_kernel,
                         cudaFuncAttributeMaxDynamicSharedMemorySize, SMEMSZ);
    dim3 grid(HH, BATCH);
    conv_mma_kernel<<<grid, THREADS, SMEMSZ>>>(x, bias, out);
}

// round 17
// speedup vs baseline: 1.0582x; 1.0582x over previous
#include <cuda_runtime.h>
#include <cuda_fp16.h>
#include <stdint.h>

#define BATCH 16
#define CIN   128
#define HH    128
#define WW    128
#define OCH   256
#define HW    (HH*WW)
#define KTOT  1152.0f
#define BADCNT 576.0f
#define NASSIGN 2048

// ---------------- scratch (no allocations allowed) ----------------
__device__ float g_pm  [BATCH*HW];
__device__ float g_bad [BATCH*HW];
__device__ float g_csum[BATCH*HW];
__device__ float g_ccnt[BATCH*HW];
__device__ float g_csum4[BATCH*4*HW];   // per-cg partials from xprep
__device__ float g_ccnt4[BATCH*4*HW];
// B fragments (single fp16 chain), packed for LDS.128 (2 n-tiles per load):
// [ tap*4+cg ][ ntp16 ][ kt2 ][ lane32 ][ jj2 ][ r2 ]  (u32); block = 4096 words = 16KB
#define WF_WORDS (36*4096)
__device__ uint32_t g_wf[WF_WORDS];
// Pre-transposed fp16 input: [b][cg][rp 130][wc 132][ch 32], 16B-chunk swizzled.
__device__ __align__(128) uint16_t g_xt[(size_t)BATCH*4*130*4224];

__device__ __forceinline__ bool nan_bits(float v) {
    return (__float_as_uint(v) & 0x7fffffffu) > 0x7f800000u;
}
__device__ __forceinline__ uint32_t smem_u32(const void* p) {
    return (uint32_t)__cvta_generic_to_shared(p);
}
__device__ __forceinline__ void cp16(uint32_t dst, const void* src) {
    asm volatile("cp.async.cg.shared.global [%0], [%1], 16;" :: "r"(dst), "l"(src));
}
__device__ __forceinline__ void mma16816(float* c, const uint32_t* a, uint32_t b0, uint32_t b1) {
    asm volatile(
        "mma.sync.aligned.m16n8k16.row.col.f32.f16.f16.f32 "
        "{%0,%1,%2,%3}, {%4,%5,%6,%7}, {%8,%9}, {%0,%1,%2,%3};"
        : "+f"(c[0]), "+f"(c[1]), "+f"(c[2]), "+f"(c[3])
        : "r"(a[0]), "r"(a[1]), "r"(a[2]), "r"(a[3]), "r"(b0), "r"(b1));
}

// ---------------- stats1b: reduce 4 cg partials -> per-pixel ----------------
__global__ void stats1b_kernel() {
    int idx = blockIdx.x * blockDim.x + threadIdx.x;
    if (idx >= BATCH * HW) return;
    int b  = idx / HW;
    int hw = idx - b * HW;
    float s = 0.f, cnt = 0.f;
    #pragma unroll
    for (int cg = 0; cg < 4; cg++) {
        s   += g_csum4[(b * 4 + cg) * HW + hw];
        cnt += g_ccnt4[(b * 4 + cg) * HW + hw];
    }
    g_csum[idx] = s;
    g_ccnt[idx] = cnt;
}

__global__ void stats2_kernel() {
    int idx = blockIdx.x * blockDim.x + threadIdx.x;
    if (idx >= BATCH * HW) return;
    int b  = idx / HW;
    int hw = idx - b * HW;
    int oh = hw / WW;
    int ow = hw - oh * WW;
    float vs = 0.f, cnt = 0.f;
    #pragma unroll
    for (int kh = -1; kh <= 1; kh++) {
        int ih = oh + kh;
        if (ih < 0 || ih >= HH) continue;
        #pragma unroll
        for (int kw = -1; kw <= 1; kw++) {
            int iw = ow + kw;
            if (iw < 0 || iw >= WW) continue;
            int g = b * HW + ih * WW + iw;
            vs  += g_csum[g];
            cnt += g_ccnt[g];
        }
    }
    float valid = KTOT - cnt;
    g_pm[idx]  = vs / fmaxf(valid, 1.f);
    g_bad[idx] = (cnt >= BADCNT) ? 1.f : 0.f;
}

// ---------------- weight prep: fp16 round into packed B-fragment layout ----------------
__global__ void wprep_kernel(const float* __restrict__ w) {
    int idx = blockIdx.x * blockDim.x + threadIdx.x;
    if (idx >= WF_WORDS) return;
    int r    = idx & 1;
    int jj   = (idx >> 1) & 1;
    int lane = (idx >> 2) & 31;
    int kt   = (idx >> 7) & 1;
    int ntp  = (idx >> 8) & 15;
    int tcg  = idx >> 12;              // tap*4+cg
    int cg   = tcg & 3;
    int tap  = tcg >> 2;

    int nt = ntp * 2 + jj;
    int oc = nt * 8 + (lane >> 2);
    int c0 = cg * 32 + kt * 16 + (lane & 3) * 2 + r * 8;

    uint32_t pack = 0;
    #pragma unroll
    for (int e = 0; e < 2; e++) {
        float wv = w[((size_t)oc * CIN + (c0 + e)) * 9 + tap];
        pack |= (uint32_t)__half_as_ushort(__float2half_rn(wv)) << (e * 16);
    }
    g_wf[idx] = pack;
}

// ---------------- x prep: fp16 transpose + swizzle + fused channel stats ----------------
__global__ void xprep_kernel(const float* __restrict__ x) {
    __shared__ float tile[32 * 133];
    const int rp = blockIdx.x;   // 0..129
    const int cg = blockIdx.y;
    const int b  = blockIdx.z;
    const int t  = threadIdx.x;
    uint32_t* dst = (uint32_t*)(g_xt + (((size_t)(b * 4 + cg) * 130 + rp) * 4224));

    if (rp == 0 || rp == 129) {
        for (int i = t; i < 2112; i += 256) dst[i] = 0;
        return;
    }
    const int row = rp - 1;
    const float* src = x + ((size_t)(b * CIN + cg * 32) * HH + row) * WW;
    for (int i = t; i < 4096; i += 256) {
        int c = i >> 7, col = i & 127;
        tile[c * 133 + col + 1] = src[(size_t)c * HW + col];
    }
    if (t < 128) {
        int c = t & 31, which = t >> 5;
        int wc = (which == 0) ? 0 : (128 + which);
        tile[c * 133 + wc] = 0.f;
    }
    __syncthreads();
    for (int i = t; i < 2112; i += 256) {
        int wc = i >> 4, cp = i & 15;
        float f0 = tile[(2 * cp) * 133 + wc];
        float f1 = tile[(2 * cp + 1) * 133 + wc];
        uint32_t h0 = __half_as_ushort(__float2half_rn(f0));
        uint32_t h1 = __half_as_ushort(__float2half_rn(f1));
        int chunk  = cp >> 2;
        int chunks = (chunk ^ (wc & 3) ^ ((wc >> 2) & 3)) & 3;
        dst[wc * 16 + chunks * 4 + (cp & 3)] = (h1 << 16) | h0;
    }
    if (t < 128) {
        float s = 0.f, cnt = 0.f;
        #pragma unroll 8
        for (int c = 0; c < 32; c++) {
            float v = tile[c * 133 + t + 1];
            bool n = nan_bits(v);
            cnt += n ? 1.f : 0.f;
            s   += n ? 0.f : v;
        }
        int o = (b * 4 + cg) * HW + row * WW + t;
        g_csum4[o] = s;
        g_ccnt4[o] = cnt;
    }
}

// ---------------- main conv: persistent, seamless cross-row pipeline ----------------
// Grid 148, 512 thr/CTA, 16 warps (2m x 8n). Each CTA: 13-14 assignments (oh,b).
// Per assignment: M=128 x N=256, K=1152 = 36 taps. Cadence-2 barriers, lead-2,
// 4-deep af/bf/raw rings that run continuously across assignments.
#define THREADS 512
#define RAWBYTES 8448

#define OFF_BF   0u               // 4 x 16384 = 65536
#define OFF_AF   65536u           // 4 x 8192  = 32768
#define OFF_RAW  98304u           // 4 x 8448  = 33792
#define OFF_PMH  132096u          // 2 x 256
#define OFF_BAD  132608u          // 2 x 512
#define OFF_BIAS 133632u          // 1024
#define SMEMSZ   134656u

__device__ __forceinline__ void build_af(uint32_t* af, const char* raw,
                                         const uint16_t* pmh, int kw, int tid) {
    // a0:{m,k} a1:{m+8,k} a2:{m,k+8} a3:{m+8,k+8}
    #pragma unroll
    for (int it = 0; it < 4; it++) {
        int w    = tid + it * THREADS;
        int reg  = w & 3;
        int ln   = (w >> 2) & 31;
        int tile = w >> 7;
        int kt   = tile & 1;
        int mt   = tile >> 1;
        int m    = mt * 16 + ((reg & 1) << 3) + (ln >> 2);
        int k    = kt * 16 + ((reg >> 1) << 3) + (ln & 3) * 2;
        int wc   = m + kw;
        int chunks = ((k >> 3) ^ (wc & 3) ^ ((wc >> 2) & 3)) & 3;
        uint32_t off = (uint32_t)(wc * 64 + chunks * 16 + (k & 7) * 2);
        uint32_t pair = *(const uint32_t*)(raw + off);
        uint32_t pmv  = (uint32_t)pmh[m];
        uint32_t lo = pair & 0xffffu, hi = pair >> 16;
        if ((lo & 0x7fffu) > 0x7c00u) lo = pmv;
        if ((hi & 0x7fffu) > 0x7c00u) hi = pmv;
        af[w] = (hi << 16) | lo;
    }
}

__device__ __forceinline__ void mma_tap(float acc[4][4][4], const uint32_t* af,
                                        const uint32_t* bf, int mt0, int ntp0, int lane) {
    #pragma unroll
    for (int kt = 0; kt < 2; kt++) {
        uint32_t a[4][4];
        #pragma unroll
        for (int i = 0; i < 4; i++) {
            uint4 av = *(const uint4*)&af[(((mt0 + i) * 2 + kt) * 32 + lane) * 4];
            a[i][0] = av.x; a[i][1] = av.y; a[i][2] = av.z; a[i][3] = av.w;
        }
        #pragma unroll
        for (int jp = 0; jp < 2; jp++) {
            uint4 bv = *(const uint4*)&bf[(((ntp0 + jp) * 2 + kt) * 32 + lane) * 4];
            #pragma unroll
            for (int i = 0; i < 4; i++) {
                mma16816(acc[i][jp * 2],     a[i], bv.x, bv.y);
                mma16816(acc[i][jp * 2 + 1], a[i], bv.z, bv.w);
            }
        }
    }
}

__device__ __forceinline__ void stage_row_to(uint32_t dst_addr, int a_t, int Rt, int tid) {
    int cg = Rt / 3, kh = Rt - cg * 3;
    int oh = a_t & 127, b = a_t >> 7;
    const char* src = (const char*)(g_xt + (((size_t)(b * 4 + cg) * 130 + (oh + kh)) * 4224));
    cp16(dst_addr + (uint32_t)tid * 16u, src + tid * 16);
    if (tid < 16) cp16(dst_addr + (uint32_t)(512 + tid) * 16u, src + (512 + tid) * 16);
}

// One pipeline phase. S in [0,3), PH in [0,12) compile-time: every SMEM slot,
// weight-tap index and kw constant-folds; only gmem coords are runtime.
template<int S, int PH>
__device__ __forceinline__ void phase(float acc[4][4][4], char* sm, uint32_t smb,
                                      int a_num, int ai, int mt0, int ntp0,
                                      int lane, int tid) {
    constexpr int T = S * 12 + PH;
    // --- bf prefetch: tap (T+2) mod 36 (weights repeat across assignments) ---
    {
        constexpr int tw  = (T + 2) % 36;
        constexpr int Rw  = tw / 3, kww = tw % 3;
        constexpr int tcg = ((Rw % 3) * 3 + kww) * 4 + (Rw / 3);
        constexpr uint32_t bslot = (uint32_t)(((T + 2) % 4) * 16384);
        const char* srcB = (const char*)g_wf + (size_t)tcg * 16384;
        uint32_t d = smb + OFF_BF + bslot + (uint32_t)tid * 16u;
        cp16(d,        srcB + tid * 16);
        cp16(d + 8192, srcB + 8192 + tid * 16);
    }
    // --- raw stage: global row (cur_row + 2); may belong to next assignment ---
    if constexpr ((PH % 3) == 0) {
        constexpr int c  = S * 4 + PH / 3 + 2;
        constexpr int dj = c / 12;        // 0, or 1 for next assignment's rows 0,1
        constexpr int Rt = c % 12;
        constexpr uint32_t rslot = (uint32_t)((c % 4) * RAWBYTES);
        int a_t = a_num + dj * 148;
        if (a_t < NASSIGN)
            stage_row_to(smb + OFF_RAW + rslot, a_t, Rt, tid);
    }
    asm volatile("cp.async.commit_group;");
    // --- pm/bad prefetch for next assignment (used from PH>=10 of this seg) ---
    if constexpr (S == 2 && PH == 0) {
        int a_nx = a_num + 148;
        if (a_nx < NASSIGN && tid < 128) {
            int g = (a_nx >> 7) * HW + (a_nx & 127) * WW + tid;
            ((uint16_t*)(sm + OFF_PMH))[(((ai + 1) & 1) << 7) + tid] =
                __half_as_ushort(__float2half_rn(g_pm[g]));
            ((float*)(sm + OFF_BAD))[(((ai + 1) & 1) << 7) + tid] = g_bad[g];
        }
    }
    // --- build tap T+2 ---
    {
        constexpr int kwb = (PH + 2) % 3;
        constexpr uint32_t braw = (uint32_t)((((S * 12 + PH + 2) / 3) % 4) * RAWBYTES);
        constexpr uint32_t bafs = (uint32_t)(((T + 2) % 4) * 8192);
        constexpr int poff = (S == 2 && PH >= 10) ? 1 : 0;
        const uint16_t* pmp = (const uint16_t*)(sm + OFF_PMH) + (((ai + poff) & 1) << 7);
        build_af((uint32_t*)(sm + OFF_AF + bafs), sm + OFF_RAW + braw, pmp, kwb, tid);
    }
    // --- mma tap T ---
    mma_tap(acc, (const uint32_t*)(sm + OFF_AF + (uint32_t)((T % 4) * 8192)),
            (const uint32_t*)(sm + OFF_BF + (uint32_t)((T % 4) * 16384)),
            mt0, ntp0, lane);
    if constexpr (PH & 1) {
        asm volatile("cp.async.wait_group 0;");
        __syncthreads();
    }
}

template<int S>
__device__ __forceinline__ void segment(float acc[4][4][4], char* sm, uint32_t smb,
                                        int a_num, int ai, int mt0, int ntp0,
                                        int lane, int tid) {
    phase<S,0>(acc, sm, smb, a_num, ai, mt0, ntp0, lane, tid);
    phase<S,1>(acc, sm, smb, a_num, ai, mt0, ntp0, lane, tid);
    phase<S,2>(acc, sm, smb, a_num, ai, mt0, ntp0, lane, tid);
    phase<S,3>(acc, sm, smb, a_num, ai, mt0, ntp0, lane, tid);
    phase<S,4>(acc, sm, smb, a_num, ai, mt0, ntp0, lane, tid);
    phase<S,5>(acc, sm, smb, a_num, ai, mt0, ntp0, lane, tid);
    phase<S,6>(acc, sm, smb, a_num, ai, mt0, ntp0, lane, tid);
    phase<S,7>(acc, sm, smb, a_num, ai, mt0, ntp0, lane, tid);
    phase<S,8>(acc, sm, smb, a_num, ai, mt0, ntp0, lane, tid);
    phase<S,9>(acc, sm, smb, a_num, ai, mt0, ntp0, lane, tid);
    phase<S,10>(acc, sm, smb, a_num, ai, mt0, ntp0, lane, tid);
    phase<S,11>(acc, sm, smb, a_num, ai, mt0, ntp0, lane, tid);
}

__global__ __launch_bounds__(THREADS, 1)
void conv_mma_kernel(const float* __restrict__ x,
                     const float* __restrict__ bias,
                     float* __restrict__ out)
{
    extern __shared__ char sm[];
    uint16_t* s_pmh  = (uint16_t*)(sm + OFF_PMH);
    float*    s_bad  = (float*)(sm + OFF_BAD);
    float*    s_bias = (float*)(sm + OFF_BIAS);
    const uint32_t smb = smem_u32(sm);

    const int tid  = threadIdx.x;
    const int lane = tid & 31;
    const int wid  = tid >> 5;
    const int bid  = blockIdx.x;
    const int mt0  = (wid >> 3) * 4;
    const int ntp0 = (wid & 7) * 2;
    const int n_a  = (bid < 124) ? 14 : 13;   // 2048 = 13*148 + 124

    if (tid < 256) s_bias[tid] = bias[tid];
    if (tid < 128) {
        int g = (bid >> 7) * HW + (bid & 127) * WW + tid;
        s_pmh[tid] = __half_as_ushort(__float2half_rn(g_pm[g]));
        s_bad[tid] = g_bad[g];
    }

    float acc[4][4][4];
    #pragma unroll
    for (int i = 0; i < 4; i++)
        #pragma unroll
        for (int j = 0; j < 4; j++)
            #pragma unroll
            for (int r = 0; r < 4; r++) acc[i][j][r] = 0.f;

    // ---- prologue: stage rows 0,1; bf taps 0,1; build taps 0,1 ----
    stage_row_to(smb + OFF_RAW,            bid, 0, tid);
    stage_row_to(smb + OFF_RAW + RAWBYTES, bid, 1, tid);
    asm volatile("cp.async.commit_group;");
    asm volatile("cp.async.wait_group 0;");
    __syncthreads();
    {   // bf taps 0 (tcg=0) and 1 (tap1: R=0,kw=1 -> tcg=4... compute: (0*3+kw)*4+0)
        const char* s0 = (const char*)g_wf + (size_t)((0 * 3 + 0) * 4 + 0) * 16384;
        const char* s1 = (const char*)g_wf + (size_t)((0 * 3 + 1) * 4 + 0) * 16384;
        uint32_t d0 = smb + OFF_BF + (uint32_t)tid * 16u;
        uint32_t d1 = smb + OFF_BF + 16384u + (uint32_t)tid * 16u;
        cp16(d0, s0 + tid * 16); cp16(d0 + 8192, s0 + 8192 + tid * 16);
        cp16(d1, s1 + tid * 16); cp16(d1 + 8192, s1 + 8192 + tid * 16);
        asm volatile("cp.async.commit_group;");
    }
    build_af((uint32_t*)(sm + OFF_AF),        sm + OFF_RAW, s_pmh, 0, tid);
    build_af((uint32_t*)(sm + OFF_AF + 8192), sm + OFF_RAW, s_pmh, 1, tid);
    asm volatile("cp.async.wait_group 0;");
    __syncthreads();

    // ---- persistent loop over assignments ----
    int a_num = bid;
    #pragma unroll 1
    for (int ai = 0; ai < n_a; ai++) {
        segment<0>(acc, sm, smb, a_num, ai, mt0, ntp0, lane, tid);
        segment<1>(acc, sm, smb, a_num, ai, mt0, ntp0, lane, tid);
        segment<2>(acc, sm, smb, a_num, ai, mt0, ntp0, lane, tid);

        // epilogue for assignment a_num: register-only reads, no barrier needed
        const float NANF = __uint_as_float(0x7fc00000u);
        const int oh = a_num & 127, b = a_num >> 7;
        const float* badp = s_bad + ((ai & 1) << 7);
        #pragma unroll
        for (int i = 0; i < 4; i++) {
            #pragma unroll
            for (int r = 0; r < 4; r++) {
                int m = (mt0 + i) * 16 + ((r >> 1) << 3) + (lane >> 2);
                bool isbad = badp[m] != 0.f;
                #pragma unroll
                for (int j = 0; j < 4; j++) {
                    int n = ((wid & 7) * 4 + j) * 8 + (lane & 3) * 2 + (r & 1);
                    float v = acc[i][j][r] + s_bias[n];
                    out[(((size_t)b * OCH + n) * HH + oh) * WW + m] = isbad ? NANF : v;
                    acc[i][j][r] = 0.f;
                }
            }
        }
        a_num += 148;
    }
}

// ---------------------------------------------------------------------------
extern "C" void kernel_launch(void* const* d_in, const int* in_sizes, int n_in,
                              void* d_out, int out_size) {
    const float* x    = (const float*)d_in[0];
    const float* wk   = (const float*)d_in[1];
    const float* bias = (const float*)d_in[2];
    float* out        = (float*)d_out;

    int npix = BATCH * HW;
    {
        dim3 g(130, 4, BATCH);
        xprep_kernel<<<g, 256>>>(x);
    }
    stats1b_kernel<<<(npix + 255) / 256, 256>>>();
    stats2_kernel<<<(npix + 255) / 256, 256>>>();
    wprep_kernel<<<(WF_WORDS + 255) / 256, 256>>>(wk);

    cudaFuncSetAttribute(conv_mma_kernel,
                         cudaFuncAttributeMaxDynamicSharedMemorySize, SMEMSZ);
    conv_mma_kernel<<<148, THREADS, SMEMSZ>>>(x, bias, out);
}